// round 9
// baseline (speedup 1.0000x reference)
#include <cuda_runtime.h>
#include <cuda_bf16.h>
#include <stdint.h>
#include <math.h>

// ---------------------------------------------------------------- constants
#define BATCH   2
#define NQ      16384
#define NATOMS  1024
#define KDIM    256
#define ODIM    256
#define NROWS   (BATCH * NQ)
#define OMEGA0  30.0f
#define EPSD    1e-4f

#define BM      128
#define BN      128
#define BKC     32
#define NCHUNK  (KDIM / BKC)     // 8

// SMEM map (compact swizzled tiles: 32B rows, XOR bit7->bit4)
#define SL      4096             // one K16 slice (128 rows x 32B)
#define A_ST    16384
#define B_ST    16384
#define X_ST    16384            // fp32 X chunk 128x32 (128B rows, SW128)
#define OFF_A   0                // 2 stages: 0, 16384
#define OFF_B   32768            // 2 stages: 32768, 49152
#define OFF_X   65536            // 2 stages: 65536, 81920
#define OFF_ATOM 49152           // overlays B stage 1 (prologue only)
#define OFF_OMEGA 98304
#define OFF_PART  98816
#define SM_BYTES  100352
#define EPI_STRIDE 132

static __device__ __nv_bfloat16 g_Whi[ODIM * KDIM];
static __device__ __nv_bfloat16 g_Wlo[ODIM * KDIM];
static __device__ float4        g_atom4[BATCH * NATOMS];

// ---------------------------------------------------------------- helpers
__device__ __forceinline__ uint32_t smem_u32(const void* p) {
    uint32_t a;
    asm("{ .reg .u64 t; cvta.to.shared.u64 t, %1; cvt.u32.u64 %0, t; }" : "=r"(a) : "l"(p));
    return a;
}
__device__ __forceinline__ uint32_t swz(uint32_t o)   { return o ^ ((o >> 3) & 0x70); }
__device__ __forceinline__ uint32_t swz32(uint32_t o) { return o ^ ((o >> 3) & 0x10); }

__device__ __forceinline__ void sts_u4(uint32_t a, uint32_t x, uint32_t y,
                                       uint32_t z, uint32_t w) {
    asm volatile("st.shared.v4.b32 [%0], {%1,%2,%3,%4};" :: "r"(a), "r"(x), "r"(y), "r"(z), "r"(w));
}
__device__ __forceinline__ void cp16(uint32_t dst, const void* src) {
    asm volatile("cp.async.cg.shared.global [%0], [%1], 16;" :: "r"(dst), "l"(src));
}
#define CP_COMMIT() asm volatile("cp.async.commit_group;")
#define CP_WAIT0()  asm volatile("cp.async.wait_group 0;")

#define LDSM4(r, a) \
    asm volatile("ldmatrix.sync.aligned.m8n8.x4.shared.b16 {%0,%1,%2,%3}, [%4];" \
        : "=r"((r)[0]), "=r"((r)[1]), "=r"((r)[2]), "=r"((r)[3]) : "r"(a))

__device__ __forceinline__ void mma_bf16(float* c, const uint32_t* a,
                                         uint32_t b0, uint32_t b1) {
    asm volatile(
        "mma.sync.aligned.m16n8k16.row.col.f32.bf16.bf16.f32 "
        "{%0,%1,%2,%3}, {%4,%5,%6,%7}, {%8,%9}, {%0,%1,%2,%3};"
        : "+f"(c[0]), "+f"(c[1]), "+f"(c[2]), "+f"(c[3])
        : "r"(a[0]), "r"(a[1]), "r"(a[2]), "r"(a[3]), "r"(b0), "r"(b1));
}
__device__ __forceinline__ uint32_t packsplit(float x, float y, uint32_t& lo) {
    uint32_t h;
    asm("cvt.rn.bf16x2.f32 %0, %1, %2;" : "=r"(h) : "f"(y), "f"(x));
    float hx = __uint_as_float(h << 16);
    float hy = __uint_as_float(h & 0xffff0000u);
    float rx = x - hx, ry = y - hy;
    asm("cvt.rn.bf16x2.f32 %0, %1, %2;" : "=r"(lo) : "f"(ry), "f"(rx));
    return h;
}

// ---------------------------------------------------------------- prep: W split + atom pack
__global__ __launch_bounds__(256)
void prep_kernel(const float* __restrict__ W, const float* __restrict__ atoms)
{
    int b = blockIdx.x;
    if (b < (ODIM * KDIM) / 256) {
        int i = b * 256 + threadIdx.x;
        float w = W[i];
        __nv_bfloat16 h = __float2bfloat16(w);
        g_Whi[i] = h;
        g_Wlo[i] = __float2bfloat16(w - __bfloat162float(h));
    } else {
        int i = (b - (ODIM * KDIM) / 256) * 256 + threadIdx.x;
        float ax = atoms[i*3], ay = atoms[i*3+1], az = atoms[i*3+2];
        g_atom4[i] = make_float4(ax, ay, az, fmaf(ax, ax, fmaf(ay, ay, az*az)));
    }
}

// ---------------------------------------------------------------- fused kernel
__global__ __launch_bounds__(256, 2)
void siren_fused(const float* __restrict__ X, const float* __restrict__ Q,
                 const float* __restrict__ bias,
                 const float* __restrict__ fw1, const float* __restrict__ fb1,
                 const float* __restrict__ fw2, const float* __restrict__ fb2,
                 float* __restrict__ out)
{
    extern __shared__ char sb[];
    const uint32_t sbase = smem_u32(sb);

    const int tid  = threadIdx.x;
    const int lane = tid & 31;
    const int wid  = tid >> 5;
    const int gRow0 = (blockIdx.x >> 1) * BM;
    const int gCol0 = (blockIdx.x & 1) * BN;
    const int batch = (gRow0 >= NQ) ? 1 : 0;

    const int warpM = (wid & 3) * 32;
    const int warpN = (wid >> 2) * 64;
    const int lr = lane >> 2;
    const int lc = (lane & 3) * 2;
    const int l7 = lane & 7, g = lane >> 3;
    const uint32_t aoff = swz32((uint32_t)((warpM + l7 + (g & 1) * 8) * 32 + ((g >> 1) & 1) * 16));
    const uint32_t boff = swz32((uint32_t)((warpN + l7 + (g >> 1) * 8) * 32 + (g & 1) * 16));

    // ---- loaders ------------------------------------------------------
    auto prefB = [&](int c) {
        const int n = tid >> 1, q = tid & 1;
        const uint32_t base = sbase + OFF_B + (uint32_t)(c & 1) * B_ST + q * 8192;
        const uint32_t d0 = base + swz32((uint32_t)(n * 32));
        const int gs = (gCol0 + n) * KDIM + c * BKC + q * 16;
        cp16(d0,             g_Whi + gs);
        cp16(d0 ^ 16,        g_Whi + gs + 8);
        cp16(d0 + SL,        g_Wlo + gs);
        cp16((d0 + SL) ^ 16, g_Wlo + gs + 8);
    };
    auto prefX = [&](int c) {
        const uint32_t base = sbase + OFF_X + (uint32_t)(c & 1) * X_ST;
        const float* src = X + (size_t)gRow0 * KDIM + c * BKC;
#pragma unroll
        for (int i = 0; i < 4; ++i) {
            int u = tid + i * 256;
            cp16(base + swz((uint32_t)u * 16), src + (size_t)(u >> 3) * KDIM + (u & 7) * 4);
        }
    };
    auto convertX = [&](int c) {
        const char* xs = sb + OFF_X + (uint32_t)(c & 1) * X_ST;
        const int r = tid >> 1, h = tid & 1;
        const uint32_t xb = swz((uint32_t)(r * 128 + h * 64));
        float4 v0 = *(const float4*)(xs + xb);
        float4 v1 = *(const float4*)(xs + (xb ^ 16));
        float4 v2 = *(const float4*)(xs + (xb ^ 32));
        float4 v3 = *(const float4*)(xs + (xb ^ 48));
        uint32_t h0, h1, h2, h3, h4, h5, h6, h7;
        uint32_t l0, l1, l2, l3, l4, l5, l6, l7v;
        h0 = packsplit(v0.x, v0.y, l0);  h1 = packsplit(v0.z, v0.w, l1);
        h2 = packsplit(v1.x, v1.y, l2);  h3 = packsplit(v1.z, v1.w, l3);
        h4 = packsplit(v2.x, v2.y, l4);  h5 = packsplit(v2.z, v2.w, l5);
        h6 = packsplit(v3.x, v3.y, l6);  h7 = packsplit(v3.z, v3.w, l7v);
        const uint32_t ab = sbase + OFF_A + (uint32_t)(c & 1) * A_ST + h * 8192
                          + swz32((uint32_t)(r * 32));
        sts_u4(ab,             h0, h1, h2, h3);
        sts_u4(ab ^ 16,        h4, h5, h6, h7);
        sts_u4(ab + SL,        l0, l1, l2, l3);
        sts_u4((ab + SL) ^ 16, l4, l5, l6, l7v);
    };

    // ---- prologue: one cp group {X0, X1, B0, atoms} ----
    prefX(0);
    prefX(1);
    prefB(0);
    {
        const float4* ap = g_atom4 + batch * NATOMS;
#pragma unroll
        for (int i = 0; i < 4; ++i) {
            int lin = tid + i * 256;
            cp16(sbase + OFF_ATOM + lin * 16, ap + lin);
        }
    }
    CP_COMMIT();
    CP_WAIT0();
    __syncthreads();

    // ---- omega min-dist scan (2 threads/query) ----
    {
        const int qi = tid & 127, qq = tid >> 7;
        const float* qp = Q + (size_t)(gRow0 + qi) * 3;
        float qx = qp[0], qy = qp[1], qz = qp[2];
        float nqx = -2.f * qx, nqy = -2.f * qy, nqz = -2.f * qz;
        const float4* at = (const float4*)(sb + OFF_ATOM) + qq * 512;
        float m0 = 3.4e38f, m1 = 3.4e38f;
#pragma unroll 4
        for (int j = 0; j < 512; j += 2) {
            float4 a0 = at[j], a1 = at[j + 1];
            m0 = fminf(m0, fmaf(a0.x, nqx, fmaf(a0.y, nqy, fmaf(a0.z, nqz, a0.w))));
            m1 = fminf(m1, fmaf(a1.x, nqx, fmaf(a1.y, nqy, fmaf(a1.z, nqz, a1.w))));
        }
        ((float*)(sb + OFF_PART))[qq * 128 + qi] = fminf(m0, m1);
    }
    convertX(0);                // A(0); published by the next barrier
    __syncthreads();            // atom reads + X0 reads done; partials visible

    if (tid < 128) {            // freq-net + omega finalize
        const float* part = (const float*)(sb + OFF_PART);
        float m = fminf(part[tid], part[128 + tid]);
        const float* qp = Q + (size_t)(gRow0 + tid) * 3;
        float qx = qp[0], qy = qp[1], qz = qp[2];
        float qsq = fmaf(qx, qx, fmaf(qy, qy, qz * qz));
        float mind = sqrtf(fmaxf(m + qsq, EPSD));
        float ls = __ldg(fb2);
#pragma unroll
        for (int j = 0; j < 16; ++j) {
            float z = fmaf(__ldg(fw1 + 3*j), qx,
                      fmaf(__ldg(fw1 + 3*j + 1), qy,
                      fmaf(__ldg(fw1 + 3*j + 2), qz, __ldg(fb1 + j))));
            float sp = fmaxf(z, 0.0f) + log1pf(expf(-fabsf(z)));
            ls = fmaf(__ldg(fw2 + j), sp, ls);
        }
        ls = fminf(fmaxf(ls, 0.0f), 5.0f);
        ((float*)(sb + OFF_OMEGA))[tid] = OMEGA0 * (1.0f + ls * expf(-mind));
    }

    float acc[2][8][4];
#pragma unroll
    for (int i = 0; i < 2; ++i)
#pragma unroll
        for (int j = 0; j < 8; ++j)
#pragma unroll
            for (int k = 0; k < 4; ++k) acc[i][j][k] = 0.0f;

    // ---- main loop: wait -> barrier -> prefetch -> compute -> convert ----
    // Race-free by construction: every stage overwrite (prefX/prefB/convertX)
    // is issued only after a barrier that postdates all readers of that stage.
#pragma unroll 1
    for (int c = 0; c < NCHUNK; ++c) {
        CP_WAIT0();             // group {X(c+1), B(c)} from iter c-1 landed
        __syncthreads();        // publish A(c) conversion + all prior reads
        if (c + 2 < NCHUNK) prefX(c + 2);
        if (c + 1 < NCHUNK) prefB(c + 1);
        CP_COMMIT();

        const uint32_t Ast = sbase + OFF_A + (uint32_t)(c & 1) * A_ST;
        const uint32_t Bst = sbase + OFF_B + (uint32_t)(c & 1) * B_ST;
#pragma unroll
        for (int s = 0; s < 2; ++s) {
            const uint32_t ab = Ast + s * 8192 + aoff;
            const uint32_t bb = Bst + s * 8192 + boff;
            uint32_t ah[2][4], al[2][4], bq[4][4];
            LDSM4(ah[0], ab);
            LDSM4(ah[1], ab + 512);
            LDSM4(al[0], ab + SL);
            LDSM4(al[1], ab + SL + 512);
#pragma unroll
            for (int p = 0; p < 4; ++p) LDSM4(bq[p], bb + p * 512);
            // pass 1: hi*HI
#pragma unroll
            for (int mt = 0; mt < 2; ++mt)
#pragma unroll
                for (int p = 0; p < 4; ++p) {
                    mma_bf16(acc[mt][2*p],   ah[mt], bq[p][0], bq[p][1]);
                    mma_bf16(acc[mt][2*p+1], ah[mt], bq[p][2], bq[p][3]);
                }
            // pass 2: lo*HI
#pragma unroll
            for (int mt = 0; mt < 2; ++mt)
#pragma unroll
                for (int p = 0; p < 4; ++p) {
                    mma_bf16(acc[mt][2*p],   al[mt], bq[p][0], bq[p][1]);
                    mma_bf16(acc[mt][2*p+1], al[mt], bq[p][2], bq[p][3]);
                }
            // pass 3: hi*LO
#pragma unroll
            for (int p = 0; p < 4; ++p) LDSM4(bq[p], bb + SL + p * 512);
#pragma unroll
            for (int mt = 0; mt < 2; ++mt)
#pragma unroll
                for (int p = 0; p < 4; ++p) {
                    mma_bf16(acc[mt][2*p],   ah[mt], bq[p][0], bq[p][1]);
                    mma_bf16(acc[mt][2*p+1], ah[mt], bq[p][2], bq[p][3]);
                }
        }
        if (c + 1 < NCHUNK) convertX(c + 1);
    }
    __syncthreads();            // all tile reads done; smem free

    // ---- epilogue: sin(omega*(acc+bias)) -> SMEM -> coalesced STG ----
    float* stg = (float*)sb;
    const float* omg = (const float*)(sb + OFF_OMEGA);
#pragma unroll
    for (int mt = 0; mt < 2; ++mt) {
        int r0 = warpM + mt * 16 + lr;
        float o0 = omg[r0], o1 = omg[r0 + 8];
#pragma unroll
        for (int nt = 0; nt < 8; ++nt) {
            int c0 = warpN + nt * 8 + lc;
            float b0 = __ldg(bias + gCol0 + c0), b1 = __ldg(bias + gCol0 + c0 + 1);
            float* a = acc[mt][nt];
            *(float2*)(stg + r0 * EPI_STRIDE + c0) =
                make_float2(__sinf(o0 * (a[0] + b0)), __sinf(o0 * (a[1] + b1)));
            *(float2*)(stg + (r0 + 8) * EPI_STRIDE + c0) =
                make_float2(__sinf(o1 * (a[2] + b0)), __sinf(o1 * (a[3] + b1)));
        }
    }
    __syncthreads();
#pragma unroll
    for (int i = 0; i < 16; ++i) {
        int lin = tid + i * 256;
        int rr = lin >> 5, c4 = (lin & 31) * 4;
        *(float4*)(out + (size_t)(gRow0 + rr) * ODIM + gCol0 + c4) =
            *(const float4*)(stg + rr * EPI_STRIDE + c4);
    }
}

// ---------------------------------------------------------------- launch
extern "C" void kernel_launch(void* const* d_in, const int* in_sizes, int n_in,
                              void* d_out, int out_size)
{
    const float* x     = (const float*)d_in[0];
    const float* q     = (const float*)d_in[1];
    const float* atoms = (const float*)d_in[2];
    const float* W     = (const float*)d_in[3];
    const float* bias  = (const float*)d_in[4];
    const float* fw1   = (const float*)d_in[5];
    const float* fb1   = (const float*)d_in[6];
    const float* fw2   = (const float*)d_in[7];
    const float* fb2   = (const float*)d_in[8];
    float* out = (float*)d_out;
    (void)in_sizes; (void)n_in; (void)out_size;

    cudaFuncSetAttribute(siren_fused, cudaFuncAttributeMaxDynamicSharedMemorySize, SM_BYTES);

    prep_kernel<<<(ODIM * KDIM) / 256 + (BATCH * NATOMS) / 256, 256>>>(W, atoms);
    siren_fused<<<(NROWS / BM) * (ODIM / BN), 256, SM_BYTES>>>(x, q, bias, fw1, fb1, fw2, fb2, out);
}

// round 10
// speedup vs baseline: 1.0881x; 1.0881x over previous
#include <cuda_runtime.h>
#include <cuda_bf16.h>
#include <stdint.h>
#include <math.h>

// ---------------------------------------------------------------- constants
#define BATCH   2
#define NQ      16384
#define NATOMS  1024
#define KDIM    256
#define ODIM    256
#define NROWS   (BATCH * NQ)
#define OMEGA0  30.0f
#define EPSD    1e-4f

#define BM      128
#define BN      128
#define BKC     32
#define NCHUNK  (KDIM / BKC)     // 8
#define NTHREADS 512

// SMEM map (compact swizzled tiles: 32B rows, XOR bit7->bit4)
#define SL      4096             // one K16 slice (128 rows x 32B)
#define A_ST    16384
#define B_ST    16384
#define X_ST    16384            // fp32 X chunk 128x32 (128B rows, SW128)
#define OFF_A   0                // 2 stages: 0, 16384
#define OFF_B   32768            // 2 stages: 32768, 49152
#define OFF_X   65536            // 2 stages: 65536, 81920
#define OFF_ATOM 49152           // overlays B stage 1 (prologue only)
#define OFF_OMEGA 98304          // 128 floats
#define OFF_PART  98816          // 4 x 128 floats
#define SM_BYTES  101376
#define EPI_STRIDE 132

static __device__ __nv_bfloat16 g_Whi[ODIM * KDIM];
static __device__ __nv_bfloat16 g_Wlo[ODIM * KDIM];
static __device__ float4        g_atom4[BATCH * NATOMS];

// ---------------------------------------------------------------- helpers
__device__ __forceinline__ uint32_t smem_u32(const void* p) {
    uint32_t a;
    asm("{ .reg .u64 t; cvta.to.shared.u64 t, %1; cvt.u32.u64 %0, t; }" : "=r"(a) : "l"(p));
    return a;
}
__device__ __forceinline__ uint32_t swz(uint32_t o)   { return o ^ ((o >> 3) & 0x70); }
__device__ __forceinline__ uint32_t swz32(uint32_t o) { return o ^ ((o >> 3) & 0x10); }

__device__ __forceinline__ void sts_u4(uint32_t a, uint32_t x, uint32_t y,
                                       uint32_t z, uint32_t w) {
    asm volatile("st.shared.v4.b32 [%0], {%1,%2,%3,%4};" :: "r"(a), "r"(x), "r"(y), "r"(z), "r"(w));
}
__device__ __forceinline__ void cp16(uint32_t dst, const void* src) {
    asm volatile("cp.async.cg.shared.global [%0], [%1], 16;" :: "r"(dst), "l"(src));
}
#define CP_COMMIT() asm volatile("cp.async.commit_group;")
#define CP_WAIT0()  asm volatile("cp.async.wait_group 0;")

#define LDSM4(r, a) \
    asm volatile("ldmatrix.sync.aligned.m8n8.x4.shared.b16 {%0,%1,%2,%3}, [%4];" \
        : "=r"((r)[0]), "=r"((r)[1]), "=r"((r)[2]), "=r"((r)[3]) : "r"(a))

__device__ __forceinline__ void mma_bf16(float* c, const uint32_t* a,
                                         uint32_t b0, uint32_t b1) {
    asm volatile(
        "mma.sync.aligned.m16n8k16.row.col.f32.bf16.bf16.f32 "
        "{%0,%1,%2,%3}, {%4,%5,%6,%7}, {%8,%9}, {%0,%1,%2,%3};"
        : "+f"(c[0]), "+f"(c[1]), "+f"(c[2]), "+f"(c[3])
        : "r"(a[0]), "r"(a[1]), "r"(a[2]), "r"(a[3]), "r"(b0), "r"(b1));
}
__device__ __forceinline__ uint32_t packsplit(float x, float y, uint32_t& lo) {
    uint32_t h;
    asm("cvt.rn.bf16x2.f32 %0, %1, %2;" : "=r"(h) : "f"(y), "f"(x));
    float hx = __uint_as_float(h << 16);
    float hy = __uint_as_float(h & 0xffff0000u);
    float rx = x - hx, ry = y - hy;
    asm("cvt.rn.bf16x2.f32 %0, %1, %2;" : "=r"(lo) : "f"(ry), "f"(rx));
    return h;
}

// ---------------------------------------------------------------- prep: W split + atom pack
__global__ __launch_bounds__(256)
void prep_kernel(const float* __restrict__ W, const float* __restrict__ atoms)
{
    int b = blockIdx.x;
    if (b < (ODIM * KDIM) / 256) {
        int i = b * 256 + threadIdx.x;
        float w = W[i];
        __nv_bfloat16 h = __float2bfloat16(w);
        g_Whi[i] = h;
        g_Wlo[i] = __float2bfloat16(w - __bfloat162float(h));
    } else {
        int i = (b - (ODIM * KDIM) / 256) * 256 + threadIdx.x;
        float ax = atoms[i*3], ay = atoms[i*3+1], az = atoms[i*3+2];
        g_atom4[i] = make_float4(ax, ay, az, fmaf(ax, ax, fmaf(ay, ay, az*az)));
    }
}

// ---------------------------------------------------------------- fused kernel
__global__ __launch_bounds__(NTHREADS, 2)
void siren_fused(const float* __restrict__ X, const float* __restrict__ Q,
                 const float* __restrict__ bias,
                 const float* __restrict__ fw1, const float* __restrict__ fb1,
                 const float* __restrict__ fw2, const float* __restrict__ fb2,
                 float* __restrict__ out)
{
    extern __shared__ char sb[];
    const uint32_t sbase = smem_u32(sb);

    const int tid  = threadIdx.x;
    const int lane = tid & 31;
    const int wid  = tid >> 5;               // 0..15
    const int gRow0 = (blockIdx.x >> 1) * BM;
    const int gCol0 = (blockIdx.x & 1) * BN;
    const int batch = (gRow0 >= NQ) ? 1 : 0;

    const int warpM = (wid & 3) * 32;        // 4 M-groups
    const int warpN = (wid >> 2) * 32;       // 4 N-groups
    const int lr = lane >> 2;
    const int lc = (lane & 3) * 2;
    const int l7 = lane & 7, g = lane >> 3;
    const uint32_t aoff = swz32((uint32_t)((warpM + l7 + (g & 1) * 8) * 32 + ((g >> 1) & 1) * 16));
    const uint32_t boff = swz32((uint32_t)((warpN + l7 + (g >> 1) * 8) * 32 + (g & 1) * 16));

    // ---- loaders (512 threads) ------------------------------------------
    auto prefB = [&](int c) {
        const int n = tid >> 2, q = (tid >> 1) & 1, e = tid & 1;
        const uint32_t d0 = sbase + OFF_B + (uint32_t)(c & 1) * B_ST + q * 8192
                          + (swz32((uint32_t)(n * 32)) ^ (uint32_t)(e * 16));
        const int gs = (gCol0 + n) * KDIM + c * BKC + q * 16 + e * 8;
        cp16(d0,      g_Whi + gs);
        cp16(d0 + SL, g_Wlo + gs);
    };
    auto prefX = [&](int c) {
        const uint32_t base = sbase + OFF_X + (uint32_t)(c & 1) * X_ST;
        const float* src = X + (size_t)gRow0 * KDIM + c * BKC;
#pragma unroll
        for (int i = 0; i < 2; ++i) {
            int u = tid + i * NTHREADS;
            cp16(base + swz((uint32_t)u * 16), src + (size_t)(u >> 3) * KDIM + (u & 7) * 4);
        }
    };
    auto convertX = [&](int c) {
        const char* xs = sb + OFF_X + (uint32_t)(c & 1) * X_ST;
        const int r = tid >> 2, qd = tid & 3;
        const uint32_t xb = swz((uint32_t)(r * 128 + qd * 32));
        float4 v0 = *(const float4*)(xs + xb);
        float4 v1 = *(const float4*)(xs + (xb ^ 16));
        uint32_t h0, h1, h2, h3, l0, l1, l2, l3;
        h0 = packsplit(v0.x, v0.y, l0);  h1 = packsplit(v0.z, v0.w, l1);
        h2 = packsplit(v1.x, v1.y, l2);  h3 = packsplit(v1.z, v1.w, l3);
        const uint32_t ab = sbase + OFF_A + (uint32_t)(c & 1) * A_ST + (qd >> 1) * 8192
                          + (swz32((uint32_t)(r * 32)) ^ (uint32_t)((qd & 1) * 16));
        sts_u4(ab,      h0, h1, h2, h3);
        sts_u4(ab + SL, l0, l1, l2, l3);
    };

    // ---- prologue: one cp group {X0, X1, B0, atoms} ----
    prefX(0);
    prefX(1);
    prefB(0);
    {
        const float4* ap = g_atom4 + batch * NATOMS;
#pragma unroll
        for (int i = 0; i < 2; ++i) {
            int lin = tid + i * NTHREADS;
            cp16(sbase + OFF_ATOM + lin * 16, ap + lin);
        }
    }
    CP_COMMIT();
    CP_WAIT0();
    __syncthreads();

    // ---- omega min-dist scan (4 threads/query) ----
    {
        const int qi = tid & 127, qq = tid >> 7;        // qq in 0..3
        const float* qp = Q + (size_t)(gRow0 + qi) * 3;
        float qx = qp[0], qy = qp[1], qz = qp[2];
        float nqx = -2.f * qx, nqy = -2.f * qy, nqz = -2.f * qz;
        const float4* at = (const float4*)(sb + OFF_ATOM) + qq * 256;
        float m0 = 3.4e38f, m1 = 3.4e38f;
#pragma unroll 4
        for (int j = 0; j < 256; j += 2) {
            float4 a0 = at[j], a1 = at[j + 1];
            m0 = fminf(m0, fmaf(a0.x, nqx, fmaf(a0.y, nqy, fmaf(a0.z, nqz, a0.w))));
            m1 = fminf(m1, fmaf(a1.x, nqx, fmaf(a1.y, nqy, fmaf(a1.z, nqz, a1.w))));
        }
        ((float*)(sb + OFF_PART))[qq * 128 + qi] = fminf(m0, m1);
    }
    convertX(0);                // A(0); published by the next barrier
    __syncthreads();            // atom + X0 reads done; partials visible

    if (tid < 128) {            // freq-net + omega finalize
        const float* part = (const float*)(sb + OFF_PART);
        float m = fminf(fminf(part[tid], part[128 + tid]),
                        fminf(part[256 + tid], part[384 + tid]));
        const float* qp = Q + (size_t)(gRow0 + tid) * 3;
        float qx = qp[0], qy = qp[1], qz = qp[2];
        float qsq = fmaf(qx, qx, fmaf(qy, qy, qz * qz));
        float mind = sqrtf(fmaxf(m + qsq, EPSD));
        float ls = __ldg(fb2);
#pragma unroll
        for (int j = 0; j < 16; ++j) {
            float z = fmaf(__ldg(fw1 + 3*j), qx,
                      fmaf(__ldg(fw1 + 3*j + 1), qy,
                      fmaf(__ldg(fw1 + 3*j + 2), qz, __ldg(fb1 + j))));
            float sp = fmaxf(z, 0.0f) + log1pf(expf(-fabsf(z)));
            ls = fmaf(__ldg(fw2 + j), sp, ls);
        }
        ls = fminf(fmaxf(ls, 0.0f), 5.0f);
        ((float*)(sb + OFF_OMEGA))[tid] = OMEGA0 * (1.0f + ls * expf(-mind));
    }

    float acc[2][4][4];
#pragma unroll
    for (int i = 0; i < 2; ++i)
#pragma unroll
        for (int j = 0; j < 4; ++j)
#pragma unroll
            for (int k = 0; k < 4; ++k) acc[i][j][k] = 0.0f;

    // ---- main loop: wait -> barrier -> prefetch -> compute -> convert ----
    // Race-free: every stage overwrite happens after a barrier postdating
    // all readers of that stage (same schedule as R9).
#pragma unroll 1
    for (int c = 0; c < NCHUNK; ++c) {
        CP_WAIT0();             // group {X(c+1), B(c)} from iter c-1 landed
        __syncthreads();        // publish A(c) conversion + all prior reads
        if (c + 2 < NCHUNK) prefX(c + 2);
        if (c + 1 < NCHUNK) prefB(c + 1);
        CP_COMMIT();

        const uint32_t Ast = sbase + OFF_A + (uint32_t)(c & 1) * A_ST;
        const uint32_t Bst = sbase + OFF_B + (uint32_t)(c & 1) * B_ST;
#pragma unroll
        for (int s = 0; s < 2; ++s) {
            const uint32_t ab = Ast + s * 8192 + aoff;
            const uint32_t bb = Bst + s * 8192 + boff;
            uint32_t ah[2][4], al[2][4], bq[2][4];
            LDSM4(ah[0], ab);
            LDSM4(ah[1], ab + 512);
            LDSM4(al[0], ab + SL);
            LDSM4(al[1], ab + SL + 512);
            LDSM4(bq[0], bb);
            LDSM4(bq[1], bb + 512);
            // pass 1: hi*HI
#pragma unroll
            for (int mt = 0; mt < 2; ++mt)
#pragma unroll
                for (int p = 0; p < 2; ++p) {
                    mma_bf16(acc[mt][2*p],   ah[mt], bq[p][0], bq[p][1]);
                    mma_bf16(acc[mt][2*p+1], ah[mt], bq[p][2], bq[p][3]);
                }
            // pass 2: lo*HI
#pragma unroll
            for (int mt = 0; mt < 2; ++mt)
#pragma unroll
                for (int p = 0; p < 2; ++p) {
                    mma_bf16(acc[mt][2*p],   al[mt], bq[p][0], bq[p][1]);
                    mma_bf16(acc[mt][2*p+1], al[mt], bq[p][2], bq[p][3]);
                }
            // pass 3: hi*LO (reload B frags as lo)
            LDSM4(bq[0], bb + SL);
            LDSM4(bq[1], bb + SL + 512);
#pragma unroll
            for (int mt = 0; mt < 2; ++mt)
#pragma unroll
                for (int p = 0; p < 2; ++p) {
                    mma_bf16(acc[mt][2*p],   ah[mt], bq[p][0], bq[p][1]);
                    mma_bf16(acc[mt][2*p+1], ah[mt], bq[p][2], bq[p][3]);
                }
        }
        if (c + 1 < NCHUNK) convertX(c + 1);
    }
    __syncthreads();            // all tile reads done; smem free

    // ---- epilogue: sin(omega*(acc+bias)) -> SMEM -> coalesced STG ----
    float* stg = (float*)sb;
    const float* omg = (const float*)(sb + OFF_OMEGA);
#pragma unroll
    for (int mt = 0; mt < 2; ++mt) {
        int r0 = warpM + mt * 16 + lr;
        float o0 = omg[r0], o1 = omg[r0 + 8];
#pragma unroll
        for (int nt = 0; nt < 4; ++nt) {
            int c0 = warpN + nt * 8 + lc;
            float b0 = __ldg(bias + gCol0 + c0), b1 = __ldg(bias + gCol0 + c0 + 1);
            float* a = acc[mt][nt];
            *(float2*)(stg + r0 * EPI_STRIDE + c0) =
                make_float2(__sinf(o0 * (a[0] + b0)), __sinf(o0 * (a[1] + b1)));
            *(float2*)(stg + (r0 + 8) * EPI_STRIDE + c0) =
                make_float2(__sinf(o1 * (a[2] + b0)), __sinf(o1 * (a[3] + b1)));
        }
    }
    __syncthreads();
#pragma unroll
    for (int i = 0; i < 8; ++i) {
        int lin = tid + i * NTHREADS;
        int rr = lin >> 5, c4 = (lin & 31) * 4;
        *(float4*)(out + (size_t)(gRow0 + rr) * ODIM + gCol0 + c4) =
            *(const float4*)(stg + rr * EPI_STRIDE + c4);
    }
}

// ---------------------------------------------------------------- launch
extern "C" void kernel_launch(void* const* d_in, const int* in_sizes, int n_in,
                              void* d_out, int out_size)
{
    const float* x     = (const float*)d_in[0];
    const float* q     = (const float*)d_in[1];
    const float* atoms = (const float*)d_in[2];
    const float* W     = (const float*)d_in[3];
    const float* bias  = (const float*)d_in[4];
    const float* fw1   = (const float*)d_in[5];
    const float* fb1   = (const float*)d_in[6];
    const float* fw2   = (const float*)d_in[7];
    const float* fb2   = (const float*)d_in[8];
    float* out = (float*)d_out;
    (void)in_sizes; (void)n_in; (void)out_size;

    cudaFuncSetAttribute(siren_fused, cudaFuncAttributeMaxDynamicSharedMemorySize, SM_BYTES);

    prep_kernel<<<(ODIM * KDIM) / 256 + (BATCH * NATOMS) / 256, 256>>>(W, atoms);
    siren_fused<<<(NROWS / BM) * (ODIM / BN), NTHREADS, SM_BYTES>>>(x, q, bias, fw1, fb1, fw2, fb2, out);
}